// round 10
// baseline (speedup 1.0000x reference)
#include <cuda_runtime.h>
#include <cuda_bf16.h>
#include <cstdint>
#include <math.h>

#define N_NODES 50000
#define N_EDGES 800000
#define D 128

// ---------------- static scratch ----------------
__device__ float g_h  [N_NODES * D];   // ping
__device__ float g_h2 [N_NODES * D];   // pong
__device__ float g_hn [N_NODES * D];   // aggregated neighbors
__device__ float g_tmp[N_NODES * D];   // self-GEMM partial
__device__ int   g_deg[N_NODES];
__device__ float g_invdeg[N_NODES];
__device__ int   g_rowptr[N_NODES + 1];
__device__ int   g_pos[N_NODES];
__device__ int   g_col[N_EDGES];
__device__ __align__(16) __nv_bfloat16 g_Whi[8 * 16384];
__device__ __align__(16) __nv_bfloat16 g_Wlo[8 * 16384];

// ---------------- helpers ----------------
__device__ __forceinline__ uint32_t smem_u32(const void* p) {
    uint32_t a;
    asm("{ .reg .u64 t; cvta.to.shared.u64 t, %1; cvt.u32.u64 %0, t; }" : "=r"(a) : "l"(p));
    return a;
}
__device__ __forceinline__ void ldsm_x4(uint32_t* r, uint32_t addr) {
    asm volatile("ldmatrix.sync.aligned.m8n8.x4.shared.b16 {%0,%1,%2,%3}, [%4];"
                 : "=r"(r[0]), "=r"(r[1]), "=r"(r[2]), "=r"(r[3]) : "r"(addr));
}
__device__ __forceinline__ void ldsm_x2t(uint32_t* r, uint32_t addr) {
    asm volatile("ldmatrix.sync.aligned.m8n8.x2.trans.shared.b16 {%0,%1}, [%2];"
                 : "=r"(r[0]), "=r"(r[1]) : "r"(addr));
}
__device__ __forceinline__ void mma_bf16(float* c, const uint32_t* a, const uint32_t* b) {
    asm volatile(
        "mma.sync.aligned.m16n8k16.row.col.f32.bf16.bf16.f32 "
        "{%0,%1,%2,%3}, {%4,%5,%6,%7}, {%8,%9}, {%0,%1,%2,%3};"
        : "+f"(c[0]), "+f"(c[1]), "+f"(c[2]), "+f"(c[3])
        : "r"(a[0]), "r"(a[1]), "r"(a[2]), "r"(a[3]), "r"(b[0]), "r"(b[1]));
}
__device__ __forceinline__ void split_pack4(float4 v, uint2& hi, uint2& lo) {
    __nv_bfloat16 h0 = __float2bfloat16(v.x);
    __nv_bfloat16 h1 = __float2bfloat16(v.y);
    __nv_bfloat16 h2 = __float2bfloat16(v.z);
    __nv_bfloat16 h3 = __float2bfloat16(v.w);
    __nv_bfloat16 l0 = __float2bfloat16(v.x - __bfloat162float(h0));
    __nv_bfloat16 l1 = __float2bfloat16(v.y - __bfloat162float(h1));
    __nv_bfloat16 l2 = __float2bfloat16(v.z - __bfloat162float(h2));
    __nv_bfloat16 l3 = __float2bfloat16(v.w - __bfloat162float(h3));
    hi.x = (uint32_t)__bfloat16_as_ushort(h0) | ((uint32_t)__bfloat16_as_ushort(h1) << 16);
    hi.y = (uint32_t)__bfloat16_as_ushort(h2) | ((uint32_t)__bfloat16_as_ushort(h3) << 16);
    lo.x = (uint32_t)__bfloat16_as_ushort(l0) | ((uint32_t)__bfloat16_as_ushort(l1) << 16);
    lo.y = (uint32_t)__bfloat16_as_ushort(l2) | ((uint32_t)__bfloat16_as_ushort(l3) << 16);
}

// ---------------- GEMM tile config (M tile = 64, 2 blocks/SM) ----------------
#define PITCH 272
#define MTILE 64
#define A_TILE_BYTES (MTILE * PITCH)   // 17408
#define B_TILE_BYTES (128 * PITCH)     // 34816
#define SMEM_TOTAL_BYTES (2 * A_TILE_BYTES + 2 * B_TILE_BYTES)  // 104448
#define STG_PITCH 132                  // fp32 staging pitch (528 B)
// layout: As_hi | As_lo | Bs_hi | Bs_lo ; fp32 staging overlays Bs

__device__ __forceinline__ void load_split_A(const float* __restrict__ src, int row0, int n,
                                             char* As_hi, char* As_lo, int tid) {
    #pragma unroll 4
    for (int i = tid; i < 2048; i += 256) {
        int r = i >> 5, c = (i & 31) << 2;
        int gr = row0 + r;
        float4 v = make_float4(0.f, 0.f, 0.f, 0.f);
        if (gr < n) v = *(const float4*)(src + (size_t)gr * D + c);
        uint2 h, l;
        split_pack4(v, h, l);
        *(uint2*)(As_hi + r * PITCH + c * 2) = h;
        *(uint2*)(As_lo + r * PITCH + c * 2) = l;
    }
}

__device__ __forceinline__ void stage_split_A(const float* __restrict__ stg,
                                              char* As_hi, char* As_lo, int tid) {
    #pragma unroll 4
    for (int i = tid; i < 2048; i += 256) {
        int r = i >> 5, c = (i & 31) << 2;
        float4 v = *(const float4*)(stg + r * STG_PITCH + c);
        uint2 h, l;
        split_pack4(v, h, l);
        *(uint2*)(As_hi + r * PITCH + c * 2) = h;
        *(uint2*)(As_lo + r * PITCH + c * 2) = l;
    }
}

__device__ __forceinline__ void load_B_prepped(int slot, char* Bs_hi, char* Bs_lo, int tid) {
    const __nv_bfloat16* whi = g_Whi + (size_t)slot * 16384;
    const __nv_bfloat16* wlo = g_Wlo + (size_t)slot * 16384;
    #pragma unroll 4
    for (int i = tid; i < 2048; i += 256) {
        int r = i >> 4, c = (i & 15) << 3;
        *(uint4*)(Bs_hi + r * PITCH + c * 2) = *(const uint4*)(whi + r * D + c);
        *(uint4*)(Bs_lo + r * PITCH + c * 2) = *(const uint4*)(wlo + r * D + c);
    }
}

__device__ __forceinline__ void mma_mainloop(float acc[2][4][4], uint32_t a_hi0, uint32_t b_hi0) {
    #pragma unroll
    for (int k = 0; k < 8; k++) {
        uint32_t ah[2][4], al[2][4], bh[4][2], bl[4][2];
        #pragma unroll
        for (int nt = 0; nt < 4; nt++) {
            ldsm_x2t(bh[nt], b_hi0 + (uint32_t)k * (16 * PITCH) + nt * 16);
            ldsm_x2t(bl[nt], b_hi0 + B_TILE_BYTES + (uint32_t)k * (16 * PITCH) + nt * 16);
        }
        #pragma unroll
        for (int mt = 0; mt < 2; mt++) {
            ldsm_x4(ah[mt], a_hi0 + (uint32_t)mt * (16 * PITCH) + k * 32);
            ldsm_x4(al[mt], a_hi0 + A_TILE_BYTES + (uint32_t)mt * (16 * PITCH) + k * 32);
        }
        #pragma unroll
        for (int mt = 0; mt < 2; mt++)
            #pragma unroll
            for (int nt = 0; nt < 4; nt++) {
                mma_bf16(acc[mt][nt], ah[mt], bh[nt]);
                mma_bf16(acc[mt][nt], ah[mt], bl[nt]);
                mma_bf16(acc[mt][nt], al[mt], bh[nt]);
            }
    }
}

__device__ __forceinline__ void zero_acc(float acc[2][4][4]) {
    #pragma unroll
    for (int mt = 0; mt < 2; mt++)
        #pragma unroll
        for (int nt = 0; nt < 4; nt++)
            #pragma unroll
            for (int q = 0; q < 4; q++) acc[mt][nt][q] = 0.f;
}

template <int ACT>
__device__ __forceinline__ void epilogue(float acc[2][4][4], const float* __restrict__ bias,
                                         const float* __restrict__ Cin,
                                         float* __restrict__ Cout, int row0, int n,
                                         int wm, int wn, int lane) {
    int mrow = lane >> 2;
    int mcol = (lane & 3) * 2;
    #pragma unroll
    for (int mt = 0; mt < 2; mt++)
        #pragma unroll
        for (int half = 0; half < 2; half++) {
            int gr = row0 + wm + mt * 16 + mrow + half * 8;
            if (gr < n) {
                size_t rb = (size_t)gr * D;
                #pragma unroll
                for (int nt = 0; nt < 4; nt++) {
                    int col = wn + nt * 8 + mcol;
                    float x0 = acc[mt][nt][half * 2 + 0];
                    float x1 = acc[mt][nt][half * 2 + 1];
                    if (bias) { x0 += bias[col]; x1 += bias[col + 1]; }
                    if (Cin) {
                        float2 cv = *(const float2*)(Cin + rb + col);
                        x0 += cv.x; x1 += cv.y;
                    }
                    if (ACT == 1)      { x0 = tanhf(x0); x1 = tanhf(x1); }
                    else if (ACT == 2) { x0 = x0 / (1.f + expf(-x0)); x1 = x1 / (1.f + expf(-x1)); }
                    *(float2*)(Cout + rb + col) = make_float2(x0, x1);
                }
            }
        }
}

// full single GEMM pass: Cout = act(A@W[slot] + bias + Cin)
template <int ACT>
__device__ __forceinline__ void gemm_pass(const float* __restrict__ A, int slot,
                                          const float* __restrict__ bias,
                                          const float* __restrict__ Cin,
                                          float* __restrict__ Cout, int n, int row0,
                                          char* smem) {
    char* As_hi = smem;
    char* As_lo = smem + A_TILE_BYTES;
    char* Bs_hi = smem + 2 * A_TILE_BYTES;
    int tid = threadIdx.x, lane = tid & 31, wid = tid >> 5;
    int wm = (wid & 1) * 32;
    int wn = (wid >> 1) * 32;

    load_split_A(A, row0, n, As_hi, As_lo, tid);
    load_B_prepped(slot, Bs_hi, Bs_hi + B_TILE_BYTES, tid);
    __syncthreads();

    uint32_t a_hi0 = smem_u32(As_hi) + (uint32_t)(wm + (lane & 15)) * PITCH + (lane >> 4) * 16;
    uint32_t b_hi0 = smem_u32(Bs_hi) + (uint32_t)(lane & 15) * PITCH + wn * 2;

    float acc[2][4][4];
    zero_acc(acc);
    mma_mainloop(acc, a_hi0, b_hi0);
    epilogue<ACT>(acc, bias, Cin, Cout, row0, n, wm, wn, lane);
}

// warp-per-node mean aggregation body (warp handles `node`)
__device__ __forceinline__ void agg_node(const float* __restrict__ h, float* __restrict__ hn,
                                         int node, int lane) {
    int beg = g_rowptr[node], end = g_rowptr[node + 1];
    float4 acc = make_float4(0.f, 0.f, 0.f, 0.f);
    int e = beg;
    for (; e + 4 <= end; e += 4) {
        int s0 = g_col[e], s1 = g_col[e + 1], s2 = g_col[e + 2], s3 = g_col[e + 3];
        float4 v0 = *(const float4*)(h + (size_t)s0 * D + lane * 4);
        float4 v1 = *(const float4*)(h + (size_t)s1 * D + lane * 4);
        float4 v2 = *(const float4*)(h + (size_t)s2 * D + lane * 4);
        float4 v3 = *(const float4*)(h + (size_t)s3 * D + lane * 4);
        acc.x += v0.x + v1.x + v2.x + v3.x;
        acc.y += v0.y + v1.y + v2.y + v3.y;
        acc.z += v0.z + v1.z + v2.z + v3.z;
        acc.w += v0.w + v1.w + v2.w + v3.w;
    }
    for (; e < end; e++) {
        int s = g_col[e];
        float4 v = *(const float4*)(h + (size_t)s * D + lane * 4);
        acc.x += v.x; acc.y += v.y; acc.z += v.z; acc.w += v.w;
    }
    float inv = g_invdeg[node];
    acc.x *= inv; acc.y *= inv; acc.z *= inv; acc.w *= inv;
    *(float4*)(hn + (size_t)node * D + lane * 4) = acc;
}

// ---------------- prep: zero deg + count degrees + W fp32 -> hi/lo bf16 ----------------
// slot 0: W_in1, 1: W_in2, 2..4: W_self[i], 5..7: W_neigh[i]
__global__ void prep_kernel(const float* __restrict__ W1, const float* __restrict__ W2,
                            const float* __restrict__ Wself, const float* __restrict__ Wneigh,
                            const int* __restrict__ dst) {
    int idx = blockIdx.x * blockDim.x + threadIdx.x;
    if (idx < 8 * 16384) {
        int slot = idx >> 14, off = idx & 16383;
        const float* src;
        if (slot == 0)      src = W1;
        else if (slot == 1) src = W2;
        else if (slot < 5)  src = Wself + (size_t)(slot - 2) * 16384;
        else                src = Wneigh + (size_t)(slot - 5) * 16384;
        float v = src[off];
        __nv_bfloat16 h = __float2bfloat16(v);
        g_Whi[idx] = h;
        g_Wlo[idx] = __float2bfloat16(v - __bfloat162float(h));
    }
    if (idx < N_NODES) g_deg[idx] = 0;
    // ensure all zeroing is visible before counting (separate grid pass not needed:
    // zero and count touch same idx ranges; do count in a second kernel-phase via
    // a grid-wide split: count below uses edges >= handled after __threadfence? )
    // NOTE: zero/count race avoided by doing count in count-only region below with
    // a device-wide dependency: we instead zero via this kernel and count in scan-prep
    // — simpler: count moved to count_kernel (kept separate for correctness).
}
__global__ void count_kernel(const int* __restrict__ dst) {
    int e = blockIdx.x * blockDim.x + threadIdx.x;
    if (e < N_EDGES) atomicAdd(&g_deg[dst[e]], 1);
}
__global__ void scan_kernel() {
    __shared__ int part[1024];
    const int CH = (N_NODES + 1023) / 1024;
    int t = threadIdx.x;
    int start = t * CH;
    int end = start + CH; if (end > N_NODES) end = N_NODES;
    int s = 0;
    for (int i = start; i < end; i++) s += g_deg[i];
    part[t] = s;
    __syncthreads();
    for (int off = 1; off < 1024; off <<= 1) {
        int v = 0;
        if (t >= off) v = part[t - off];
        __syncthreads();
        if (t >= off) part[t] += v;
        __syncthreads();
    }
    int run = (t == 0) ? 0 : part[t - 1];
    for (int i = start; i < end; i++) {
        g_rowptr[i] = run;
        g_pos[i]    = run;
        int d = g_deg[i];
        g_invdeg[i] = 1.0f / (float)(d > 1 ? d : 1);
        run += d;
    }
    if (t == 1023) g_rowptr[N_NODES] = part[1023];
}

// ---------------- fused fc_in ∥ CSR-fill (block-specialized) ----------------
// grid = 3907: bid%5==0 -> fc tile bid/5 (782 tiles); else fill chunk (3125 chunks)
__global__ void __launch_bounds__(256, 2)
fcfill_kernel(const float* __restrict__ A, const float* __restrict__ b1,
              const float* __restrict__ b2, float* __restrict__ Cout, int n,
              const int* __restrict__ src, const int* __restrict__ dst) {
    extern __shared__ char smem[];
    int bid = blockIdx.x;
    int tid = threadIdx.x;

    if (bid % 5 != 0) {
        // ---- fill role ----
        int fidx = bid - bid / 5 - 1;          // 0..3124
        int e = fidx * 256 + tid;
        if (e < N_EDGES) {
            int d = dst[e];
            int idx = atomicAdd(&g_pos[d], 1);
            g_col[idx] = src[e];
        }
        return;
    }

    // ---- fc role: out = tanh(A@W1+b1)@W2 + b2 ----
    char* As_hi = smem;
    char* As_lo = smem + A_TILE_BYTES;
    char* Bs_hi = smem + 2 * A_TILE_BYTES;
    float* staging = (float*)(smem + 2 * A_TILE_BYTES);  // overlays Bs

    int lane = tid & 31, wid = tid >> 5;
    int row0 = (bid / 5) * MTILE;
    int wm = (wid & 1) * 32;
    int wn = (wid >> 1) * 32;
    int mrow = lane >> 2;
    int mcol = (lane & 3) * 2;

    uint32_t a_hi0 = smem_u32(As_hi) + (uint32_t)(wm + (lane & 15)) * PITCH + (lane >> 4) * 16;
    uint32_t b_hi0 = smem_u32(Bs_hi) + (uint32_t)(lane & 15) * PITCH + wn * 2;

    float acc[2][4][4];
    zero_acc(acc);

    load_split_A(A, row0, n, As_hi, As_lo, tid);
    load_B_prepped(0, Bs_hi, Bs_hi + B_TILE_BYTES, tid);
    __syncthreads();
    mma_mainloop(acc, a_hi0, b_hi0);
    __syncthreads();

    #pragma unroll
    for (int mt = 0; mt < 2; mt++)
        #pragma unroll
        for (int half = 0; half < 2; half++) {
            int r = wm + mt * 16 + mrow + half * 8;
            #pragma unroll
            for (int nt = 0; nt < 4; nt++) {
                int col = wn + nt * 8 + mcol;
                staging[r * STG_PITCH + col]     = tanhf(acc[mt][nt][half * 2 + 0] + b1[col]);
                staging[r * STG_PITCH + col + 1] = tanhf(acc[mt][nt][half * 2 + 1] + b1[col + 1]);
            }
        }
    __syncthreads();

    stage_split_A(staging, As_hi, As_lo, tid);
    __syncthreads();

    load_B_prepped(1, Bs_hi, Bs_hi + B_TILE_BYTES, tid);
    zero_acc(acc);
    __syncthreads();

    mma_mainloop(acc, a_hi0, b_hi0);
    epilogue<0>(acc, b2, nullptr, Cout, row0, n, wm, wn, lane);
}

// ---------------- phase A: self-GEMM ∥ aggregation (block-specialized) ----------------
// grid = 7032: bid%9==0 -> GEMM tile bid/9 (782); else agg block (6250, 8 nodes each)
__global__ void __launch_bounds__(256, 2)
phaseA_kernel(const float* __restrict__ in, int slot_self,
              float* __restrict__ temp, float* __restrict__ hn, int n) {
    extern __shared__ char smem[];
    int bid = blockIdx.x;
    if (bid % 9 == 0) {
        // temp = in @ Ws  (no bias/act)
        gemm_pass<0>(in, slot_self, nullptr, nullptr, temp, n, (bid / 9) * MTILE, smem);
    } else {
        int aidx = bid - bid / 9 - 1;          // 0..6249
        int wid = threadIdx.x >> 5, lane = threadIdx.x & 31;
        int node = aidx * 8 + wid;
        if (node < n) agg_node(in, hn, node, lane);
    }
}

// ---------------- phase B: out = act(hn@Wn + temp + bias) ----------------
template <int ACT>
__global__ void __launch_bounds__(256, 2)
phaseB_kernel(const float* __restrict__ hn, int slot_neigh,
              const float* __restrict__ bias, const float* __restrict__ temp,
              float* __restrict__ Cout, int n) {
    extern __shared__ char smem[];
    gemm_pass<ACT>(hn, slot_neigh, bias, temp, Cout, n, blockIdx.x * MTILE, smem);
}

// ---------------- launch ----------------
extern "C" void kernel_launch(void* const* d_in, const int* in_sizes, int n_in,
                              void* d_out, int out_size) {
    const float* h_in    = (const float*)d_in[0];
    const int*   src     = (const int*)  d_in[1];
    const int*   dst     = (const int*)  d_in[2];
    const float* W_in1   = (const float*)d_in[3];
    const float* b_in1   = (const float*)d_in[4];
    const float* W_in2   = (const float*)d_in[5];
    const float* b_in2   = (const float*)d_in[6];
    const float* W_self  = (const float*)d_in[7];
    const float* b_self  = (const float*)d_in[8];
    const float* W_neigh = (const float*)d_in[9];
    float* out = (float*)d_out;

    cudaFuncSetAttribute(fcfill_kernel,   cudaFuncAttributeMaxDynamicSharedMemorySize, SMEM_TOTAL_BYTES);
    cudaFuncSetAttribute(phaseA_kernel,   cudaFuncAttributeMaxDynamicSharedMemorySize, SMEM_TOTAL_BYTES);
    cudaFuncSetAttribute(phaseB_kernel<1>, cudaFuncAttributeMaxDynamicSharedMemorySize, SMEM_TOTAL_BYTES);
    cudaFuncSetAttribute(phaseB_kernel<2>, cudaFuncAttributeMaxDynamicSharedMemorySize, SMEM_TOTAL_BYTES);

    float* buf0 = nullptr;
    float* buf1 = nullptr;
    float* hn   = nullptr;
    float* tmp  = nullptr;
    cudaGetSymbolAddress((void**)&buf0, g_h);
    cudaGetSymbolAddress((void**)&buf1, g_h2);
    cudaGetSymbolAddress((void**)&hn,   g_hn);
    cudaGetSymbolAddress((void**)&tmp,  g_tmp);

    const int GEMM_GRID   = (N_NODES + MTILE - 1) / MTILE;   // 782
    const int EB          = (N_EDGES + 255) / 256;           // 3125
    const int FCFILL_GRID = 3907;   // 782 fc tiles (bid%5==0) + 3125 fill chunks
    const int PHASEA_GRID = 7032;   // 782 gemm tiles (bid%9==0) + 6250 agg blocks
    const int PREP_GRID   = (8 * 16384 + 255) / 256;          // 512

    // ---- prep (W split + zero deg), count, scan ----
    prep_kernel<<<PREP_GRID, 256>>>(W_in1, W_in2, W_self, W_neigh, dst);
    count_kernel<<<EB, 256>>>(dst);
    scan_kernel<<<1, 1024>>>();

    // ---- fc_in ∥ CSR fill ----
    fcfill_kernel<<<FCFILL_GRID, 256, SMEM_TOTAL_BYTES>>>(h_in, b_in1, b_in2, buf0, N_NODES, src, dst);

    // ---- 3 SAGE layers: [self-GEMM ∥ agg] then [neigh-GEMM + accumulate] ----
    phaseA_kernel<<<PHASEA_GRID, 256, SMEM_TOTAL_BYTES>>>(buf0, 2, tmp, hn, N_NODES);
    phaseB_kernel<2><<<GEMM_GRID, 256, SMEM_TOTAL_BYTES>>>(hn, 5, b_self + 0 * D, tmp, buf1, N_NODES);

    phaseA_kernel<<<PHASEA_GRID, 256, SMEM_TOTAL_BYTES>>>(buf1, 3, tmp, hn, N_NODES);
    phaseB_kernel<2><<<GEMM_GRID, 256, SMEM_TOTAL_BYTES>>>(hn, 6, b_self + 1 * D, tmp, buf0, N_NODES);

    phaseA_kernel<<<PHASEA_GRID, 256, SMEM_TOTAL_BYTES>>>(buf0, 4, tmp, hn, N_NODES);
    phaseB_kernel<1><<<GEMM_GRID, 256, SMEM_TOTAL_BYTES>>>(hn, 7, b_self + 2 * D, tmp, out, N_NODES);
}

// round 11
// speedup vs baseline: 1.2652x; 1.2652x over previous
#include <cuda_runtime.h>
#include <cuda_bf16.h>
#include <cstdint>
#include <math.h>

#define N_NODES 50000
#define N_EDGES 800000
#define D 128

// ---------------- static scratch ----------------
__device__ float g_h [N_NODES * D];   // ping
__device__ float g_h2[N_NODES * D];   // pong
__device__ int   g_deg[N_NODES];
__device__ float g_invdeg[N_NODES];
__device__ int   g_rowptr[N_NODES + 1];
__device__ int   g_pos[N_NODES];
__device__ int   g_col[N_EDGES];
__device__ __align__(16) __nv_bfloat16 g_Whi[8 * 16384];
__device__ __align__(16) __nv_bfloat16 g_Wlo[8 * 16384];

// ---------------- helpers ----------------
__device__ __forceinline__ uint32_t smem_u32(const void* p) {
    uint32_t a;
    asm("{ .reg .u64 t; cvta.to.shared.u64 t, %1; cvt.u32.u64 %0, t; }" : "=r"(a) : "l"(p));
    return a;
}
__device__ __forceinline__ void ldsm_x4(uint32_t* r, uint32_t addr) {
    asm volatile("ldmatrix.sync.aligned.m8n8.x4.shared.b16 {%0,%1,%2,%3}, [%4];"
                 : "=r"(r[0]), "=r"(r[1]), "=r"(r[2]), "=r"(r[3]) : "r"(addr));
}
__device__ __forceinline__ void ldsm_x2t(uint32_t* r, uint32_t addr) {
    asm volatile("ldmatrix.sync.aligned.m8n8.x2.trans.shared.b16 {%0,%1}, [%2];"
                 : "=r"(r[0]), "=r"(r[1]) : "r"(addr));
}
__device__ __forceinline__ void mma_bf16(float* c, const uint32_t* a, const uint32_t* b) {
    asm volatile(
        "mma.sync.aligned.m16n8k16.row.col.f32.bf16.bf16.f32 "
        "{%0,%1,%2,%3}, {%4,%5,%6,%7}, {%8,%9}, {%0,%1,%2,%3};"
        : "+f"(c[0]), "+f"(c[1]), "+f"(c[2]), "+f"(c[3])
        : "r"(a[0]), "r"(a[1]), "r"(a[2]), "r"(a[3]), "r"(b[0]), "r"(b[1]));
}
__device__ __forceinline__ void split_pack4(float4 v, uint2& hi, uint2& lo) {
    __nv_bfloat16 h0 = __float2bfloat16(v.x);
    __nv_bfloat16 h1 = __float2bfloat16(v.y);
    __nv_bfloat16 h2 = __float2bfloat16(v.z);
    __nv_bfloat16 h3 = __float2bfloat16(v.w);
    __nv_bfloat16 l0 = __float2bfloat16(v.x - __bfloat162float(h0));
    __nv_bfloat16 l1 = __float2bfloat16(v.y - __bfloat162float(h1));
    __nv_bfloat16 l2 = __float2bfloat16(v.z - __bfloat162float(h2));
    __nv_bfloat16 l3 = __float2bfloat16(v.w - __bfloat162float(h3));
    hi.x = (uint32_t)__bfloat16_as_ushort(h0) | ((uint32_t)__bfloat16_as_ushort(h1) << 16);
    hi.y = (uint32_t)__bfloat16_as_ushort(h2) | ((uint32_t)__bfloat16_as_ushort(h3) << 16);
    lo.x = (uint32_t)__bfloat16_as_ushort(l0) | ((uint32_t)__bfloat16_as_ushort(l1) << 16);
    lo.y = (uint32_t)__bfloat16_as_ushort(l2) | ((uint32_t)__bfloat16_as_ushort(l3) << 16);
}

// ---------------- CSR build ----------------
__global__ void count_kernel(const int* __restrict__ dst) {
    int e = blockIdx.x * blockDim.x + threadIdx.x;
    if (e < N_EDGES) atomicAdd(&g_deg[dst[e]], 1);
}
__global__ void scan_kernel() {
    __shared__ int part[1024];
    const int CH = (N_NODES + 1023) / 1024;
    int t = threadIdx.x;
    int start = t * CH;
    int end = start + CH; if (end > N_NODES) end = N_NODES;
    int s = 0;
    for (int i = start; i < end; i++) s += g_deg[i];
    part[t] = s;
    __syncthreads();
    for (int off = 1; off < 1024; off <<= 1) {
        int v = 0;
        if (t >= off) v = part[t - off];
        __syncthreads();
        if (t >= off) part[t] += v;
        __syncthreads();
    }
    int run = (t == 0) ? 0 : part[t - 1];
    for (int i = start; i < end; i++) {
        g_rowptr[i] = run;
        g_pos[i]    = run;
        int d = g_deg[i];
        g_invdeg[i] = 1.0f / (float)(d > 1 ? d : 1);
        run += d;
    }
    if (t == 1023) g_rowptr[N_NODES] = part[1023];
}
__global__ void fill_kernel(const int* __restrict__ src, const int* __restrict__ dst) {
    int e = blockIdx.x * blockDim.x + threadIdx.x;
    if (e < N_EDGES) {
        int d = dst[e];
        int idx = atomicAdd(&g_pos[d], 1);
        g_col[idx] = src[e];
    }
}

// ---------------- prep: zero degrees + W fp32 -> hi/lo bf16 (8 slots) ----------------
// slot 0: W_in1, 1: W_in2, 2..4: W_self[i], 5..7: W_neigh[i]
__global__ void prep_kernel(const float* __restrict__ W1, const float* __restrict__ W2,
                            const float* __restrict__ Wself, const float* __restrict__ Wneigh) {
    int idx = blockIdx.x * blockDim.x + threadIdx.x;
    if (idx < N_NODES) g_deg[idx] = 0;
    if (idx >= 8 * 16384) return;
    int slot = idx >> 14, off = idx & 16383;
    const float* src;
    if (slot == 0)      src = W1;
    else if (slot == 1) src = W2;
    else if (slot < 5)  src = Wself + (size_t)(slot - 2) * 16384;
    else                src = Wneigh + (size_t)(slot - 5) * 16384;
    float v = src[off];
    __nv_bfloat16 h = __float2bfloat16(v);
    g_Whi[idx] = h;
    g_Wlo[idx] = __float2bfloat16(v - __bfloat162float(h));
}

// ---------------- GEMM tile config (M tile = 64, 2 blocks/SM) ----------------
#define PITCH 272
#define MTILE 64
#define A_TILE_BYTES (MTILE * PITCH)   // 17408
#define B_TILE_BYTES (128 * PITCH)     // 34816
#define SMEM_TOTAL_BYTES (2 * A_TILE_BYTES + 2 * B_TILE_BYTES)  // 104448
#define STG_PITCH 132                  // fp32 staging pitch (528 B)
// layout: As_hi | As_lo | Bs_hi | Bs_lo ; fp32 staging overlays Bs

__device__ __forceinline__ void load_split_A(const float* __restrict__ src, int row0, int n,
                                             char* As_hi, char* As_lo, int tid) {
    #pragma unroll 4
    for (int i = tid; i < 2048; i += 256) {
        int r = i >> 5, c = (i & 31) << 2;
        int gr = row0 + r;
        float4 v = make_float4(0.f, 0.f, 0.f, 0.f);
        if (gr < n) v = *(const float4*)(src + (size_t)gr * D + c);
        uint2 h, l;
        split_pack4(v, h, l);
        *(uint2*)(As_hi + r * PITCH + c * 2) = h;
        *(uint2*)(As_lo + r * PITCH + c * 2) = l;
    }
}

__device__ __forceinline__ void stage_split_A(const float* __restrict__ stg,
                                              char* As_hi, char* As_lo, int tid) {
    #pragma unroll 4
    for (int i = tid; i < 2048; i += 256) {
        int r = i >> 5, c = (i & 31) << 2;
        float4 v = *(const float4*)(stg + r * STG_PITCH + c);
        uint2 h, l;
        split_pack4(v, h, l);
        *(uint2*)(As_hi + r * PITCH + c * 2) = h;
        *(uint2*)(As_lo + r * PITCH + c * 2) = l;
    }
}

__device__ __forceinline__ void load_B_prepped(int slot, char* Bs_hi, char* Bs_lo, int tid) {
    const __nv_bfloat16* whi = g_Whi + (size_t)slot * 16384;
    const __nv_bfloat16* wlo = g_Wlo + (size_t)slot * 16384;
    #pragma unroll 4
    for (int i = tid; i < 2048; i += 256) {
        int r = i >> 4, c = (i & 15) << 3;
        *(uint4*)(Bs_hi + r * PITCH + c * 2) = *(const uint4*)(whi + r * D + c);
        *(uint4*)(Bs_lo + r * PITCH + c * 2) = *(const uint4*)(wlo + r * D + c);
    }
}

// in-block mean aggregation: warp wid handles rows [wid*8, wid*8+8).
// Writes hi/lo bf16 directly into As — byte layout identical to load_split_A (proven R7).
// Gather unrolled x8 for MLP.
__device__ __forceinline__ void agg_split_A(const float* __restrict__ h, int row0, int n,
                                            char* As_hi, char* As_lo, int wid, int lane) {
    #pragma unroll
    for (int j = 0; j < 8; j++) {
        int r = wid * 8 + j;
        int node = row0 + r;
        float4 a = make_float4(0.f, 0.f, 0.f, 0.f);
        if (node < n) {
            int beg = g_rowptr[node], end = g_rowptr[node + 1];
            int e = beg;
            for (; e + 8 <= end; e += 8) {
                float4 v0 = *(const float4*)(h + (size_t)g_col[e + 0] * D + lane * 4);
                float4 v1 = *(const float4*)(h + (size_t)g_col[e + 1] * D + lane * 4);
                float4 v2 = *(const float4*)(h + (size_t)g_col[e + 2] * D + lane * 4);
                float4 v3 = *(const float4*)(h + (size_t)g_col[e + 3] * D + lane * 4);
                float4 v4 = *(const float4*)(h + (size_t)g_col[e + 4] * D + lane * 4);
                float4 v5 = *(const float4*)(h + (size_t)g_col[e + 5] * D + lane * 4);
                float4 v6 = *(const float4*)(h + (size_t)g_col[e + 6] * D + lane * 4);
                float4 v7 = *(const float4*)(h + (size_t)g_col[e + 7] * D + lane * 4);
                a.x += (v0.x + v1.x) + (v2.x + v3.x) + (v4.x + v5.x) + (v6.x + v7.x);
                a.y += (v0.y + v1.y) + (v2.y + v3.y) + (v4.y + v5.y) + (v6.y + v7.y);
                a.z += (v0.z + v1.z) + (v2.z + v3.z) + (v4.z + v5.z) + (v6.z + v7.z);
                a.w += (v0.w + v1.w) + (v2.w + v3.w) + (v4.w + v5.w) + (v6.w + v7.w);
            }
            for (; e < end; e++) {
                float4 v = *(const float4*)(h + (size_t)g_col[e] * D + lane * 4);
                a.x += v.x; a.y += v.y; a.z += v.z; a.w += v.w;
            }
            float inv = g_invdeg[node];
            a.x *= inv; a.y *= inv; a.z *= inv; a.w *= inv;
        }
        uint2 hh, ll;
        split_pack4(a, hh, ll);
        *(uint2*)(As_hi + r * PITCH + lane * 8) = hh;
        *(uint2*)(As_lo + r * PITCH + lane * 8) = ll;
    }
}

__device__ __forceinline__ void mma_mainloop(float acc[2][4][4], uint32_t a_hi0, uint32_t b_hi0) {
    #pragma unroll
    for (int k = 0; k < 8; k++) {
        uint32_t ah[2][4], al[2][4], bh[4][2], bl[4][2];
        #pragma unroll
        for (int nt = 0; nt < 4; nt++) {
            ldsm_x2t(bh[nt], b_hi0 + (uint32_t)k * (16 * PITCH) + nt * 16);
            ldsm_x2t(bl[nt], b_hi0 + B_TILE_BYTES + (uint32_t)k * (16 * PITCH) + nt * 16);
        }
        #pragma unroll
        for (int mt = 0; mt < 2; mt++) {
            ldsm_x4(ah[mt], a_hi0 + (uint32_t)mt * (16 * PITCH) + k * 32);
            ldsm_x4(al[mt], a_hi0 + A_TILE_BYTES + (uint32_t)mt * (16 * PITCH) + k * 32);
        }
        #pragma unroll
        for (int mt = 0; mt < 2; mt++)
            #pragma unroll
            for (int nt = 0; nt < 4; nt++) {
                mma_bf16(acc[mt][nt], ah[mt], bh[nt]);
                mma_bf16(acc[mt][nt], ah[mt], bl[nt]);
                mma_bf16(acc[mt][nt], al[mt], bh[nt]);
            }
    }
}

__device__ __forceinline__ void zero_acc(float acc[2][4][4]) {
    #pragma unroll
    for (int mt = 0; mt < 2; mt++)
        #pragma unroll
        for (int nt = 0; nt < 4; nt++)
            #pragma unroll
            for (int q = 0; q < 4; q++) acc[mt][nt][q] = 0.f;
}

template <int ACT>
__device__ __forceinline__ void epilogue(float acc[2][4][4], const float* __restrict__ bias,
                                         float* __restrict__ Cout, int row0, int n,
                                         int wm, int wn, int lane) {
    int mrow = lane >> 2;
    int mcol = (lane & 3) * 2;
    #pragma unroll
    for (int mt = 0; mt < 2; mt++)
        #pragma unroll
        for (int half = 0; half < 2; half++) {
            int gr = row0 + wm + mt * 16 + mrow + half * 8;
            if (gr < n) {
                size_t rb = (size_t)gr * D;
                #pragma unroll
                for (int nt = 0; nt < 4; nt++) {
                    int col = wn + nt * 8 + mcol;
                    float x0 = acc[mt][nt][half * 2 + 0];
                    float x1 = acc[mt][nt][half * 2 + 1];
                    if (bias) { x0 += bias[col]; x1 += bias[col + 1]; }
                    if (ACT == 1)      { x0 = tanhf(x0); x1 = tanhf(x1); }
                    else if (ACT == 2) { x0 = x0 / (1.f + expf(-x0)); x1 = x1 / (1.f + expf(-x1)); }
                    *(float2*)(Cout + rb + col) = make_float2(x0, x1);
                }
            }
        }
}

// ---------------- fused fc_in: out = tanh(h@W1+b1)@W2 + b2 (proven R8/R9) ----------------
__global__ void __launch_bounds__(256, 2)
fc_fused_kernel(const float* __restrict__ A, const float* __restrict__ b1,
                const float* __restrict__ b2, float* __restrict__ Cout, int n) {
    extern __shared__ char smem[];
    char* As_hi = smem;
    char* As_lo = smem + A_TILE_BYTES;
    char* Bs_hi = smem + 2 * A_TILE_BYTES;
    float* staging = (float*)(smem + 2 * A_TILE_BYTES);  // overlays Bs region

    int tid = threadIdx.x, lane = tid & 31, wid = tid >> 5;
    int row0 = blockIdx.x * MTILE;
    int wm = (wid & 1) * 32;
    int wn = (wid >> 1) * 32;
    int mrow = lane >> 2;
    int mcol = (lane & 3) * 2;

    uint32_t a_hi0 = smem_u32(As_hi) + (uint32_t)(wm + (lane & 15)) * PITCH + (lane >> 4) * 16;
    uint32_t b_hi0 = smem_u32(Bs_hi) + (uint32_t)(lane & 15) * PITCH + wn * 2;

    float acc[2][4][4];
    zero_acc(acc);

    load_split_A(A, row0, n, As_hi, As_lo, tid);
    load_B_prepped(0, Bs_hi, Bs_hi + B_TILE_BYTES, tid);
    __syncthreads();
    mma_mainloop(acc, a_hi0, b_hi0);
    __syncthreads();

    #pragma unroll
    for (int mt = 0; mt < 2; mt++)
        #pragma unroll
        for (int half = 0; half < 2; half++) {
            int r = wm + mt * 16 + mrow + half * 8;
            #pragma unroll
            for (int nt = 0; nt < 4; nt++) {
                int col = wn + nt * 8 + mcol;
                staging[r * STG_PITCH + col]     = tanhf(acc[mt][nt][half * 2 + 0] + b1[col]);
                staging[r * STG_PITCH + col + 1] = tanhf(acc[mt][nt][half * 2 + 1] + b1[col + 1]);
            }
        }
    __syncthreads();

    stage_split_A(staging, As_hi, As_lo, tid);
    __syncthreads();

    load_B_prepped(1, Bs_hi, Bs_hi + B_TILE_BYTES, tid);
    zero_acc(acc);
    __syncthreads();

    mma_mainloop(acc, a_hi0, b_hi0);
    epilogue<0>(acc, b2, Cout, row0, n, wm, wn, lane);
}

// ---------------- fused SAGE layer with embedded agg + anti-lockstep phasing ----------------
// out = act(in@Ws + bias + mean_agg(in)@Wn)
// Co-resident blocks (bid, bid+148) take phases in opposite order so one block's
// gather (memory) overlaps the other's mainloop (tensor).
template <int ACT>
__global__ void __launch_bounds__(256, 2)
layer_kernel(const float* __restrict__ in, int slot_self, int slot_neigh,
             const float* __restrict__ bias, float* __restrict__ Cout, int n) {
    extern __shared__ char smem[];
    char* As_hi = smem;
    char* As_lo = smem + A_TILE_BYTES;
    char* Bs_hi = smem + 2 * A_TILE_BYTES;

    int tid = threadIdx.x, lane = tid & 31, wid = tid >> 5;
    int row0 = blockIdx.x * MTILE;
    int wm = (wid & 1) * 32;
    int wn = (wid >> 1) * 32;

    uint32_t a_hi0 = smem_u32(As_hi) + (uint32_t)(wm + (lane & 15)) * PITCH + (lane >> 4) * 16;
    uint32_t b_hi0 = smem_u32(Bs_hi) + (uint32_t)(lane & 15) * PITCH + wn * 2;

    float acc[2][4][4];
    zero_acc(acc);

    bool gemm_first = ((blockIdx.x / 148) & 1) == 0;

    if (gemm_first) {
        // self-GEMM, then agg+neigh-GEMM
        load_split_A(in, row0, n, As_hi, As_lo, tid);
        load_B_prepped(slot_self, Bs_hi, Bs_hi + B_TILE_BYTES, tid);
        __syncthreads();
        mma_mainloop(acc, a_hi0, b_hi0);
        __syncthreads();

        load_B_prepped(slot_neigh, Bs_hi, Bs_hi + B_TILE_BYTES, tid);
        agg_split_A(in, row0, n, As_hi, As_lo, wid, lane);
        __syncthreads();
        mma_mainloop(acc, a_hi0, b_hi0);
    } else {
        // agg+neigh-GEMM, then self-GEMM (acc accumulation is commutative)
        load_B_prepped(slot_neigh, Bs_hi, Bs_hi + B_TILE_BYTES, tid);
        agg_split_A(in, row0, n, As_hi, As_lo, wid, lane);
        __syncthreads();
        mma_mainloop(acc, a_hi0, b_hi0);
        __syncthreads();

        load_split_A(in, row0, n, As_hi, As_lo, tid);
        load_B_prepped(slot_self, Bs_hi, Bs_hi + B_TILE_BYTES, tid);
        __syncthreads();
        mma_mainloop(acc, a_hi0, b_hi0);
    }

    epilogue<ACT>(acc, bias, Cout, row0, n, wm, wn, lane);
}

// ---------------- launch ----------------
extern "C" void kernel_launch(void* const* d_in, const int* in_sizes, int n_in,
                              void* d_out, int out_size) {
    const float* h_in    = (const float*)d_in[0];
    const int*   src     = (const int*)  d_in[1];
    const int*   dst     = (const int*)  d_in[2];
    const float* W_in1   = (const float*)d_in[3];
    const float* b_in1   = (const float*)d_in[4];
    const float* W_in2   = (const float*)d_in[5];
    const float* b_in2   = (const float*)d_in[6];
    const float* W_self  = (const float*)d_in[7];
    const float* b_self  = (const float*)d_in[8];
    const float* W_neigh = (const float*)d_in[9];
    float* out = (float*)d_out;

    cudaFuncSetAttribute(fc_fused_kernel, cudaFuncAttributeMaxDynamicSharedMemorySize, SMEM_TOTAL_BYTES);
    cudaFuncSetAttribute(layer_kernel<1>, cudaFuncAttributeMaxDynamicSharedMemorySize, SMEM_TOTAL_BYTES);
    cudaFuncSetAttribute(layer_kernel<2>, cudaFuncAttributeMaxDynamicSharedMemorySize, SMEM_TOTAL_BYTES);

    float* buf0 = nullptr;
    float* buf1 = nullptr;
    cudaGetSymbolAddress((void**)&buf0, g_h);
    cudaGetSymbolAddress((void**)&buf1, g_h2);

    const int GEMM_GRID = (N_NODES + MTILE - 1) / MTILE;  // 782
    const int EB = (N_EDGES + 255) / 256;

    // ---- prep (W split + zero deg) then CSR build ----
    prep_kernel<<<512, 256>>>(W_in1, W_in2, W_self, W_neigh);
    count_kernel<<<EB, 256>>>(dst);
    scan_kernel<<<1, 1024>>>();
    fill_kernel<<<EB, 256>>>(src, dst);

    // ---- fc_in fused: buf0 = tanh(h@W1+b1)@W2 + b2 ----
    fc_fused_kernel<<<GEMM_GRID, 256, SMEM_TOTAL_BYTES>>>(h_in, b_in1, b_in2, buf0, N_NODES);

    // ---- 3 fused SAGE layers (agg embedded, anti-lockstep) ----
    layer_kernel<2><<<GEMM_GRID, 256, SMEM_TOTAL_BYTES>>>(buf0, 2, 5, b_self + 0 * D, buf1, N_NODES);
    layer_kernel<2><<<GEMM_GRID, 256, SMEM_TOTAL_BYTES>>>(buf1, 3, 6, b_self + 1 * D, buf0, N_NODES);
    layer_kernel<1><<<GEMM_GRID, 256, SMEM_TOTAL_BYTES>>>(buf0, 4, 7, b_self + 2 * D, out, N_NODES);
}

// round 12
// speedup vs baseline: 1.2689x; 1.0029x over previous
#include <cuda_runtime.h>
#include <cuda_bf16.h>
#include <cstdint>
#include <math.h>

#define N_NODES 50000
#define N_EDGES 800000
#define D 128

// ---------------- static scratch ----------------
__device__ float g_h  [N_NODES * D];   // ping
__device__ float g_h2 [N_NODES * D];   // pong
__device__ float g_hn [N_NODES * D];   // aggregated neighbors
__device__ float g_tmp[N_NODES * D];   // self-GEMM partial
__device__ int   g_deg[N_NODES];
__device__ float g_invdeg[N_NODES];
__device__ int   g_rowptr[N_NODES + 1];
__device__ int   g_pos[N_NODES];
__device__ int   g_col[N_EDGES];
__device__ __align__(16) __nv_bfloat16 g_Whi[8 * 16384];
__device__ __align__(16) __nv_bfloat16 g_Wlo[8 * 16384];

// ---------------- helpers ----------------
__device__ __forceinline__ uint32_t smem_u32(const void* p) {
    uint32_t a;
    asm("{ .reg .u64 t; cvta.to.shared.u64 t, %1; cvt.u32.u64 %0, t; }" : "=r"(a) : "l"(p));
    return a;
}
__device__ __forceinline__ void ldsm_x4(uint32_t* r, uint32_t addr) {
    asm volatile("ldmatrix.sync.aligned.m8n8.x4.shared.b16 {%0,%1,%2,%3}, [%4];"
                 : "=r"(r[0]), "=r"(r[1]), "=r"(r[2]), "=r"(r[3]) : "r"(addr));
}
__device__ __forceinline__ void ldsm_x2t(uint32_t* r, uint32_t addr) {
    asm volatile("ldmatrix.sync.aligned.m8n8.x2.trans.shared.b16 {%0,%1}, [%2];"
                 : "=r"(r[0]), "=r"(r[1]) : "r"(addr));
}
__device__ __forceinline__ void mma_bf16(float* c, const uint32_t* a, const uint32_t* b) {
    asm volatile(
        "mma.sync.aligned.m16n8k16.row.col.f32.bf16.bf16.f32 "
        "{%0,%1,%2,%3}, {%4,%5,%6,%7}, {%8,%9}, {%0,%1,%2,%3};"
        : "+f"(c[0]), "+f"(c[1]), "+f"(c[2]), "+f"(c[3])
        : "r"(a[0]), "r"(a[1]), "r"(a[2]), "r"(a[3]), "r"(b[0]), "r"(b[1]));
}
__device__ __forceinline__ void split_pack4(float4 v, uint2& hi, uint2& lo) {
    __nv_bfloat16 h0 = __float2bfloat16(v.x);
    __nv_bfloat16 h1 = __float2bfloat16(v.y);
    __nv_bfloat16 h2 = __float2bfloat16(v.z);
    __nv_bfloat16 h3 = __float2bfloat16(v.w);
    __nv_bfloat16 l0 = __float2bfloat16(v.x - __bfloat162float(h0));
    __nv_bfloat16 l1 = __float2bfloat16(v.y - __bfloat162float(h1));
    __nv_bfloat16 l2 = __float2bfloat16(v.z - __bfloat162float(h2));
    __nv_bfloat16 l3 = __float2bfloat16(v.w - __bfloat162float(h3));
    hi.x = (uint32_t)__bfloat16_as_ushort(h0) | ((uint32_t)__bfloat16_as_ushort(h1) << 16);
    hi.y = (uint32_t)__bfloat16_as_ushort(h2) | ((uint32_t)__bfloat16_as_ushort(h3) << 16);
    lo.x = (uint32_t)__bfloat16_as_ushort(l0) | ((uint32_t)__bfloat16_as_ushort(l1) << 16);
    lo.y = (uint32_t)__bfloat16_as_ushort(l2) | ((uint32_t)__bfloat16_as_ushort(l3) << 16);
}

// ---------------- CSR build ----------------
__global__ void count_kernel(const int* __restrict__ dst) {
    int e = blockIdx.x * blockDim.x + threadIdx.x;
    if (e < N_EDGES) atomicAdd(&g_deg[dst[e]], 1);
}
__global__ void scan_kernel() {
    __shared__ int part[1024];
    const int CH = (N_NODES + 1023) / 1024;
    int t = threadIdx.x;
    int start = t * CH;
    int end = start + CH; if (end > N_NODES) end = N_NODES;
    int s = 0;
    for (int i = start; i < end; i++) s += g_deg[i];
    part[t] = s;
    __syncthreads();
    for (int off = 1; off < 1024; off <<= 1) {
        int v = 0;
        if (t >= off) v = part[t - off];
        __syncthreads();
        if (t >= off) part[t] += v;
        __syncthreads();
    }
    int run = (t == 0) ? 0 : part[t - 1];
    for (int i = start; i < end; i++) {
        g_rowptr[i] = run;
        g_pos[i]    = run;
        int d = g_deg[i];
        g_invdeg[i] = 1.0f / (float)(d > 1 ? d : 1);
        run += d;
    }
    if (t == 1023) g_rowptr[N_NODES] = part[1023];
}
__global__ void fill_kernel(const int* __restrict__ src, const int* __restrict__ dst) {
    int e = blockIdx.x * blockDim.x + threadIdx.x;
    if (e < N_EDGES) {
        int d = dst[e];
        int idx = atomicAdd(&g_pos[d], 1);
        g_col[idx] = src[e];
    }
}

// ---------------- prep: zero degrees + W fp32 -> hi/lo bf16 (8 slots) ----------------
// slot 0: W_in1, 1: W_in2, 2..4: W_self[i], 5..7: W_neigh[i]
__global__ void prep_kernel(const float* __restrict__ W1, const float* __restrict__ W2,
                            const float* __restrict__ Wself, const float* __restrict__ Wneigh) {
    int idx = blockIdx.x * blockDim.x + threadIdx.x;
    if (idx < N_NODES) g_deg[idx] = 0;
    if (idx >= 8 * 16384) return;
    int slot = idx >> 14, off = idx & 16383;
    const float* src;
    if (slot == 0)      src = W1;
    else if (slot == 1) src = W2;
    else if (slot < 5)  src = Wself + (size_t)(slot - 2) * 16384;
    else                src = Wneigh + (size_t)(slot - 5) * 16384;
    float v = src[off];
    __nv_bfloat16 h = __float2bfloat16(v);
    g_Whi[idx] = h;
    g_Wlo[idx] = __float2bfloat16(v - __bfloat162float(h));
}

// ---------------- mean aggregation: one warp per node (full occupancy) ----------------
__global__ void agg_kernel(const float* __restrict__ h, float* __restrict__ hn) {
    int wid  = (blockIdx.x * blockDim.x + threadIdx.x) >> 5;
    int lane = threadIdx.x & 31;
    if (wid >= N_NODES) return;
    int beg = g_rowptr[wid], end = g_rowptr[wid + 1];
    float4 acc = make_float4(0.f, 0.f, 0.f, 0.f);
    int e = beg;
    for (; e + 4 <= end; e += 4) {
        int s0 = g_col[e], s1 = g_col[e + 1], s2 = g_col[e + 2], s3 = g_col[e + 3];
        float4 v0 = *(const float4*)(h + (size_t)s0 * D + lane * 4);
        float4 v1 = *(const float4*)(h + (size_t)s1 * D + lane * 4);
        float4 v2 = *(const float4*)(h + (size_t)s2 * D + lane * 4);
        float4 v3 = *(const float4*)(h + (size_t)s3 * D + lane * 4);
        acc.x += v0.x + v1.x + v2.x + v3.x;
        acc.y += v0.y + v1.y + v2.y + v3.y;
        acc.z += v0.z + v1.z + v2.z + v3.z;
        acc.w += v0.w + v1.w + v2.w + v3.w;
    }
    for (; e < end; e++) {
        int s = g_col[e];
        float4 v = *(const float4*)(h + (size_t)s * D + lane * 4);
        acc.x += v.x; acc.y += v.y; acc.z += v.z; acc.w += v.w;
    }
    float inv = g_invdeg[wid];
    acc.x *= inv; acc.y *= inv; acc.z *= inv; acc.w *= inv;
    *(float4*)(hn + (size_t)wid * D + lane * 4) = acc;
}

// ---------------- GEMM tile config (M tile = 64, 2 blocks/SM) ----------------
#define PITCH 272
#define MTILE 64
#define A_TILE_BYTES (MTILE * PITCH)   // 17408
#define B_TILE_BYTES (128 * PITCH)     // 34816
#define SMEM_TOTAL_BYTES (2 * A_TILE_BYTES + 2 * B_TILE_BYTES)  // 104448
#define STG_PITCH 132                  // fp32 staging pitch (528 B)
// layout: As_hi | As_lo | Bs_hi | Bs_lo ; fp32 staging overlays Bs

__device__ __forceinline__ void load_split_A(const float* __restrict__ src, int row0, int n,
                                             char* As_hi, char* As_lo, int tid) {
    #pragma unroll 4
    for (int i = tid; i < 2048; i += 256) {
        int r = i >> 5, c = (i & 31) << 2;
        int gr = row0 + r;
        float4 v = make_float4(0.f, 0.f, 0.f, 0.f);
        if (gr < n) v = *(const float4*)(src + (size_t)gr * D + c);
        uint2 h, l;
        split_pack4(v, h, l);
        *(uint2*)(As_hi + r * PITCH + c * 2) = h;
        *(uint2*)(As_lo + r * PITCH + c * 2) = l;
    }
}

__device__ __forceinline__ void stage_split_A(const float* __restrict__ stg,
                                              char* As_hi, char* As_lo, int tid) {
    #pragma unroll 4
    for (int i = tid; i < 2048; i += 256) {
        int r = i >> 5, c = (i & 31) << 2;
        float4 v = *(const float4*)(stg + r * STG_PITCH + c);
        uint2 h, l;
        split_pack4(v, h, l);
        *(uint2*)(As_hi + r * PITCH + c * 2) = h;
        *(uint2*)(As_lo + r * PITCH + c * 2) = l;
    }
}

__device__ __forceinline__ void load_B_prepped(int slot, char* Bs_hi, char* Bs_lo, int tid) {
    const __nv_bfloat16* whi = g_Whi + (size_t)slot * 16384;
    const __nv_bfloat16* wlo = g_Wlo + (size_t)slot * 16384;
    #pragma unroll 4
    for (int i = tid; i < 2048; i += 256) {
        int r = i >> 4, c = (i & 15) << 3;
        *(uint4*)(Bs_hi + r * PITCH + c * 2) = *(const uint4*)(whi + r * D + c);
        *(uint4*)(Bs_lo + r * PITCH + c * 2) = *(const uint4*)(wlo + r * D + c);
    }
}

__device__ __forceinline__ void mma_mainloop(float acc[2][4][4], uint32_t a_hi0, uint32_t b_hi0) {
    #pragma unroll
    for (int k = 0; k < 8; k++) {
        uint32_t ah[2][4], al[2][4], bh[4][2], bl[4][2];
        #pragma unroll
        for (int nt = 0; nt < 4; nt++) {
            ldsm_x2t(bh[nt], b_hi0 + (uint32_t)k * (16 * PITCH) + nt * 16);
            ldsm_x2t(bl[nt], b_hi0 + B_TILE_BYTES + (uint32_t)k * (16 * PITCH) + nt * 16);
        }
        #pragma unroll
        for (int mt = 0; mt < 2; mt++) {
            ldsm_x4(ah[mt], a_hi0 + (uint32_t)mt * (16 * PITCH) + k * 32);
            ldsm_x4(al[mt], a_hi0 + A_TILE_BYTES + (uint32_t)mt * (16 * PITCH) + k * 32);
        }
        #pragma unroll
        for (int mt = 0; mt < 2; mt++)
            #pragma unroll
            for (int nt = 0; nt < 4; nt++) {
                mma_bf16(acc[mt][nt], ah[mt], bh[nt]);
                mma_bf16(acc[mt][nt], ah[mt], bl[nt]);
                mma_bf16(acc[mt][nt], al[mt], bh[nt]);
            }
    }
}

__device__ __forceinline__ void zero_acc(float acc[2][4][4]) {
    #pragma unroll
    for (int mt = 0; mt < 2; mt++)
        #pragma unroll
        for (int nt = 0; nt < 4; nt++)
            #pragma unroll
            for (int q = 0; q < 4; q++) acc[mt][nt][q] = 0.f;
}

template <int ACT>
__device__ __forceinline__ void epilogue(float acc[2][4][4], const float* __restrict__ bias,
                                         const float* __restrict__ Cin,
                                         float* __restrict__ Cout, int row0, int n,
                                         int wm, int wn, int lane) {
    int mrow = lane >> 2;
    int mcol = (lane & 3) * 2;
    #pragma unroll
    for (int mt = 0; mt < 2; mt++)
        #pragma unroll
        for (int half = 0; half < 2; half++) {
            int gr = row0 + wm + mt * 16 + mrow + half * 8;
            if (gr < n) {
                size_t rb = (size_t)gr * D;
                #pragma unroll
                for (int nt = 0; nt < 4; nt++) {
                    int col = wn + nt * 8 + mcol;
                    float x0 = acc[mt][nt][half * 2 + 0];
                    float x1 = acc[mt][nt][half * 2 + 1];
                    if (bias) { x0 += bias[col]; x1 += bias[col + 1]; }
                    if (Cin) {
                        float2 cv = *(const float2*)(Cin + rb + col);
                        x0 += cv.x; x1 += cv.y;
                    }
                    if (ACT == 1)      { x0 = tanhf(x0); x1 = tanhf(x1); }
                    else if (ACT == 2) { x0 = x0 / (1.f + expf(-x0)); x1 = x1 / (1.f + expf(-x1)); }
                    *(float2*)(Cout + rb + col) = make_float2(x0, x1);
                }
            }
        }
}

// full single GEMM pass: Cout = act(A@W[slot] + bias + Cin)
template <int ACT>
__device__ __forceinline__ void gemm_pass(const float* __restrict__ A, int slot,
                                          const float* __restrict__ bias,
                                          const float* __restrict__ Cin,
                                          float* __restrict__ Cout, int n, int row0,
                                          char* smem) {
    char* As_hi = smem;
    char* As_lo = smem + A_TILE_BYTES;
    char* Bs_hi = smem + 2 * A_TILE_BYTES;
    int tid = threadIdx.x, lane = tid & 31, wid = tid >> 5;
    int wm = (wid & 1) * 32;
    int wn = (wid >> 1) * 32;

    load_split_A(A, row0, n, As_hi, As_lo, tid);
    load_B_prepped(slot, Bs_hi, Bs_hi + B_TILE_BYTES, tid);
    __syncthreads();

    uint32_t a_hi0 = smem_u32(As_hi) + (uint32_t)(wm + (lane & 15)) * PITCH + (lane >> 4) * 16;
    uint32_t b_hi0 = smem_u32(Bs_hi) + (uint32_t)(lane & 15) * PITCH + wn * 2;

    float acc[2][4][4];
    zero_acc(acc);
    mma_mainloop(acc, a_hi0, b_hi0);
    epilogue<ACT>(acc, bias, Cin, Cout, row0, n, wm, wn, lane);
}

// self-GEMM: tmp = in @ W[slot]
__global__ void __launch_bounds__(256, 2)
selfgemm_kernel(const float* __restrict__ in, int slot, float* __restrict__ tmp, int n) {
    extern __shared__ char smem[];
    gemm_pass<0>(in, slot, nullptr, nullptr, tmp, n, blockIdx.x * MTILE, smem);
}

// phase B: out = act(hn@Wn + tmp + bias)
template <int ACT>
__global__ void __launch_bounds__(256, 2)
phaseB_kernel(const float* __restrict__ hn, int slot_neigh,
              const float* __restrict__ bias, const float* __restrict__ tmp,
              float* __restrict__ Cout, int n) {
    extern __shared__ char smem[];
    gemm_pass<ACT>(hn, slot_neigh, bias, tmp, Cout, n, blockIdx.x * MTILE, smem);
}

// ---------------- fused fc_in: out = tanh(h@W1+b1)@W2 + b2 (proven R8/R9) ----------------
__global__ void __launch_bounds__(256, 2)
fc_fused_kernel(const float* __restrict__ A, const float* __restrict__ b1,
                const float* __restrict__ b2, float* __restrict__ Cout, int n) {
    extern __shared__ char smem[];
    char* As_hi = smem;
    char* As_lo = smem + A_TILE_BYTES;
    char* Bs_hi = smem + 2 * A_TILE_BYTES;
    float* staging = (float*)(smem + 2 * A_TILE_BYTES);  // overlays Bs region

    int tid = threadIdx.x, lane = tid & 31, wid = tid >> 5;
    int row0 = blockIdx.x * MTILE;
    int wm = (wid & 1) * 32;
    int wn = (wid >> 1) * 32;
    int mrow = lane >> 2;
    int mcol = (lane & 3) * 2;

    uint32_t a_hi0 = smem_u32(As_hi) + (uint32_t)(wm + (lane & 15)) * PITCH + (lane >> 4) * 16;
    uint32_t b_hi0 = smem_u32(Bs_hi) + (uint32_t)(lane & 15) * PITCH + wn * 2;

    float acc[2][4][4];
    zero_acc(acc);

    load_split_A(A, row0, n, As_hi, As_lo, tid);
    load_B_prepped(0, Bs_hi, Bs_hi + B_TILE_BYTES, tid);
    __syncthreads();
    mma_mainloop(acc, a_hi0, b_hi0);
    __syncthreads();

    #pragma unroll
    for (int mt = 0; mt < 2; mt++)
        #pragma unroll
        for (int half = 0; half < 2; half++) {
            int r = wm + mt * 16 + mrow + half * 8;
            #pragma unroll
            for (int nt = 0; nt < 4; nt++) {
                int col = wn + nt * 8 + mcol;
                staging[r * STG_PITCH + col]     = tanhf(acc[mt][nt][half * 2 + 0] + b1[col]);
                staging[r * STG_PITCH + col + 1] = tanhf(acc[mt][nt][half * 2 + 1] + b1[col + 1]);
            }
        }
    __syncthreads();

    stage_split_A(staging, As_hi, As_lo, tid);
    __syncthreads();

    load_B_prepped(1, Bs_hi, Bs_hi + B_TILE_BYTES, tid);
    zero_acc(acc);
    __syncthreads();

    mma_mainloop(acc, a_hi0, b_hi0);
    epilogue<0>(acc, b2, nullptr, Cout, row0, n, wm, wn, lane);
}

// ---------------- launch ----------------
extern "C" void kernel_launch(void* const* d_in, const int* in_sizes, int n_in,
                              void* d_out, int out_size) {
    const float* h_in    = (const float*)d_in[0];
    const int*   src     = (const int*)  d_in[1];
    const int*   dst     = (const int*)  d_in[2];
    const float* W_in1   = (const float*)d_in[3];
    const float* b_in1   = (const float*)d_in[4];
    const float* W_in2   = (const float*)d_in[5];
    const float* b_in2   = (const float*)d_in[6];
    const float* W_self  = (const float*)d_in[7];
    const float* b_self  = (const float*)d_in[8];
    const float* W_neigh = (const float*)d_in[9];
    float* out = (float*)d_out;

    cudaFuncSetAttribute(fc_fused_kernel,  cudaFuncAttributeMaxDynamicSharedMemorySize, SMEM_TOTAL_BYTES);
    cudaFuncSetAttribute(selfgemm_kernel,  cudaFuncAttributeMaxDynamicSharedMemorySize, SMEM_TOTAL_BYTES);
    cudaFuncSetAttribute(phaseB_kernel<1>, cudaFuncAttributeMaxDynamicSharedMemorySize, SMEM_TOTAL_BYTES);
    cudaFuncSetAttribute(phaseB_kernel<2>, cudaFuncAttributeMaxDynamicSharedMemorySize, SMEM_TOTAL_BYTES);

    // streams/events created once on the first (uncaptured) call; reused during capture
    static cudaStream_t s2 = nullptr;
    static cudaEvent_t ev[8];
    if (!s2) {
        cudaStreamCreateWithFlags(&s2, cudaStreamNonBlocking);
        for (int i = 0; i < 8; i++) cudaEventCreateWithFlags(&ev[i], cudaEventDisableTiming);
    }

    float* buf0 = nullptr;
    float* buf1 = nullptr;
    float* hn   = nullptr;
    float* tmp  = nullptr;
    cudaGetSymbolAddress((void**)&buf0, g_h);
    cudaGetSymbolAddress((void**)&buf1, g_h2);
    cudaGetSymbolAddress((void**)&hn,   g_hn);
    cudaGetSymbolAddress((void**)&tmp,  g_tmp);

    const int GEMM_GRID = (N_NODES + MTILE - 1) / MTILE;  // 782
    const int EB = (N_EDGES + 255) / 256;
    const int AGG_GRID = (N_NODES * 32 + 255) / 256;

    // ---- prep (W split + zero deg), count, scan (default stream) ----
    prep_kernel<<<512, 256>>>(W_in1, W_in2, W_self, W_neigh);
    count_kernel<<<EB, 256>>>(dst);
    scan_kernel<<<1, 1024>>>();

    // ---- fork: fill on s2 ∥ fc_fused on default ----
    cudaEventRecord(ev[0], 0);
    cudaStreamWaitEvent(s2, ev[0], 0);
    fill_kernel<<<EB, 256, 0, s2>>>(src, dst);
    cudaEventRecord(ev[1], s2);
    fc_fused_kernel<<<GEMM_GRID, 256, SMEM_TOTAL_BYTES>>>(h_in, b_in1, b_in2, buf0, N_NODES);
    cudaStreamWaitEvent(0, ev[1], 0);   // join: CSR ready before agg

    const float* lin[3]  = {buf0, buf1, buf0};
    float*       lout[3] = {buf1, buf0, out};
    int slot_self[3]  = {2, 3, 4};
    int slot_neigh[3] = {5, 6, 7};

    for (int i = 0; i < 3; i++) {
        // fork: self-GEMM on s2 ∥ agg on default
        cudaEventRecord(ev[2 + 2 * i], 0);
        cudaStreamWaitEvent(s2, ev[2 + 2 * i], 0);
        selfgemm_kernel<<<GEMM_GRID, 256, SMEM_TOTAL_BYTES, s2>>>(lin[i], slot_self[i], tmp, N_NODES);
        cudaEventRecord(ev[3 + 2 * i], s2);
        agg_kernel<<<AGG_GRID, 256>>>(lin[i], hn);
        cudaStreamWaitEvent(0, ev[3 + 2 * i], 0);
        // join: out = act(hn@Wn + tmp + bias)
        if (i < 2) {
            phaseB_kernel<2><<<GEMM_GRID, 256, SMEM_TOTAL_BYTES>>>(hn, slot_neigh[i], b_self + i * D, tmp, lout[i], N_NODES);
        } else {
            phaseB_kernel<1><<<GEMM_GRID, 256, SMEM_TOTAL_BYTES>>>(hn, slot_neigh[i], b_self + i * D, tmp, lout[i], N_NODES);
        }
    }
}

// round 13
// speedup vs baseline: 1.3961x; 1.1003x over previous
#include <cuda_runtime.h>
#include <cuda_bf16.h>
#include <cstdint>
#include <math.h>

#define N_NODES 50000
#define N_EDGES 800000
#define D 128

// ---------------- static scratch ----------------
// inter-layer features stored as bf16 hi/lo pairs (exact fp32-to-2^-17 repr)
__device__ __align__(16) __nv_bfloat16 g_hiA[N_NODES * D];
__device__ __align__(16) __nv_bfloat16 g_loA[N_NODES * D];
__device__ __align__(16) __nv_bfloat16 g_hiB[N_NODES * D];
__device__ __align__(16) __nv_bfloat16 g_loB[N_NODES * D];
__device__ float g_hn[N_NODES * D];   // aggregated neighbors (fp32)
__device__ int   g_deg[N_NODES];
__device__ float g_invdeg[N_NODES];
__device__ int   g_rowptr[N_NODES + 1];
__device__ int   g_pos[N_NODES];
__device__ int   g_col[N_EDGES];
__device__ __align__(16) __nv_bfloat16 g_Whi[8 * 16384];
__device__ __align__(16) __nv_bfloat16 g_Wlo[8 * 16384];

// ---------------- helpers ----------------
__device__ __forceinline__ uint32_t smem_u32(const void* p) {
    uint32_t a;
    asm("{ .reg .u64 t; cvta.to.shared.u64 t, %1; cvt.u32.u64 %0, t; }" : "=r"(a) : "l"(p));
    return a;
}
__device__ __forceinline__ void ldsm_x4(uint32_t* r, uint32_t addr) {
    asm volatile("ldmatrix.sync.aligned.m8n8.x4.shared.b16 {%0,%1,%2,%3}, [%4];"
                 : "=r"(r[0]), "=r"(r[1]), "=r"(r[2]), "=r"(r[3]) : "r"(addr));
}
__device__ __forceinline__ void ldsm_x2t(uint32_t* r, uint32_t addr) {
    asm volatile("ldmatrix.sync.aligned.m8n8.x2.trans.shared.b16 {%0,%1}, [%2];"
                 : "=r"(r[0]), "=r"(r[1]) : "r"(addr));
}
__device__ __forceinline__ void mma_bf16(float* c, const uint32_t* a, const uint32_t* b) {
    asm volatile(
        "mma.sync.aligned.m16n8k16.row.col.f32.bf16.bf16.f32 "
        "{%0,%1,%2,%3}, {%4,%5,%6,%7}, {%8,%9}, {%0,%1,%2,%3};"
        : "+f"(c[0]), "+f"(c[1]), "+f"(c[2]), "+f"(c[3])
        : "r"(a[0]), "r"(a[1]), "r"(a[2]), "r"(a[3]), "r"(b[0]), "r"(b[1]));
}
__device__ __forceinline__ void split_pack4(float4 v, uint2& hi, uint2& lo) {
    __nv_bfloat16 h0 = __float2bfloat16(v.x);
    __nv_bfloat16 h1 = __float2bfloat16(v.y);
    __nv_bfloat16 h2 = __float2bfloat16(v.z);
    __nv_bfloat16 h3 = __float2bfloat16(v.w);
    __nv_bfloat16 l0 = __float2bfloat16(v.x - __bfloat162float(h0));
    __nv_bfloat16 l1 = __float2bfloat16(v.y - __bfloat162float(h1));
    __nv_bfloat16 l2 = __float2bfloat16(v.z - __bfloat162float(h2));
    __nv_bfloat16 l3 = __float2bfloat16(v.w - __bfloat162float(h3));
    hi.x = (uint32_t)__bfloat16_as_ushort(h0) | ((uint32_t)__bfloat16_as_ushort(h1) << 16);
    hi.y = (uint32_t)__bfloat16_as_ushort(h2) | ((uint32_t)__bfloat16_as_ushort(h3) << 16);
    lo.x = (uint32_t)__bfloat16_as_ushort(l0) | ((uint32_t)__bfloat16_as_ushort(l1) << 16);
    lo.y = (uint32_t)__bfloat16_as_ushort(l2) | ((uint32_t)__bfloat16_as_ushort(l3) << 16);
}
__device__ __forceinline__ uint32_t split_pack2(float x0, float x1, uint32_t& lo) {
    __nv_bfloat16 h0 = __float2bfloat16(x0);
    __nv_bfloat16 h1 = __float2bfloat16(x1);
    __nv_bfloat16 l0 = __float2bfloat16(x0 - __bfloat162float(h0));
    __nv_bfloat16 l1 = __float2bfloat16(x1 - __bfloat162float(h1));
    lo = (uint32_t)__bfloat16_as_ushort(l0) | ((uint32_t)__bfloat16_as_ushort(l1) << 16);
    return (uint32_t)__bfloat16_as_ushort(h0) | ((uint32_t)__bfloat16_as_ushort(h1) << 16);
}

// ---------------- CSR build ----------------
__global__ void count_kernel(const int* __restrict__ dst) {
    int e = blockIdx.x * blockDim.x + threadIdx.x;
    if (e < N_EDGES) atomicAdd(&g_deg[dst[e]], 1);
}
__global__ void scan_kernel() {
    __shared__ int part[1024];
    const int CH = (N_NODES + 1023) / 1024;
    int t = threadIdx.x;
    int start = t * CH;
    int end = start + CH; if (end > N_NODES) end = N_NODES;
    int s = 0;
    for (int i = start; i < end; i++) s += g_deg[i];
    part[t] = s;
    __syncthreads();
    for (int off = 1; off < 1024; off <<= 1) {
        int v = 0;
        if (t >= off) v = part[t - off];
        __syncthreads();
        if (t >= off) part[t] += v;
        __syncthreads();
    }
    int run = (t == 0) ? 0 : part[t - 1];
    for (int i = start; i < end; i++) {
        g_rowptr[i] = run;
        g_pos[i]    = run;
        int d = g_deg[i];
        g_invdeg[i] = 1.0f / (float)(d > 1 ? d : 1);
        run += d;
    }
    if (t == 1023) g_rowptr[N_NODES] = part[1023];
}
__global__ void fill_kernel(const int* __restrict__ src, const int* __restrict__ dst) {
    int e = blockIdx.x * blockDim.x + threadIdx.x;
    if (e < N_EDGES) {
        int d = dst[e];
        int idx = atomicAdd(&g_pos[d], 1);
        g_col[idx] = src[e];
    }
}

// ---------------- prep: zero degrees + W fp32 -> hi/lo bf16 (8 slots) ----------------
__global__ void prep_kernel(const float* __restrict__ W1, const float* __restrict__ W2,
                            const float* __restrict__ Wself, const float* __restrict__ Wneigh) {
    int idx = blockIdx.x * blockDim.x + threadIdx.x;
    if (idx < N_NODES) g_deg[idx] = 0;
    if (idx >= 8 * 16384) return;
    int slot = idx >> 14, off = idx & 16383;
    const float* src;
    if (slot == 0)      src = W1;
    else if (slot == 1) src = W2;
    else if (slot < 5)  src = Wself + (size_t)(slot - 2) * 16384;
    else                src = Wneigh + (size_t)(slot - 5) * 16384;
    float v = src[off];
    __nv_bfloat16 h = __float2bfloat16(v);
    g_Whi[idx] = h;
    g_Wlo[idx] = __float2bfloat16(v - __bfloat162float(h));
}

// ---------------- mean aggregation over bf16-hi features (half traffic) ----------------
__global__ void agg_bf16_kernel(const __nv_bfloat16* __restrict__ hhi, float* __restrict__ hn) {
    int wid  = (blockIdx.x * blockDim.x + threadIdx.x) >> 5;
    int lane = threadIdx.x & 31;
    if (wid >= N_NODES) return;
    int beg = g_rowptr[wid], end = g_rowptr[wid + 1];
    float4 acc = make_float4(0.f, 0.f, 0.f, 0.f);
    int e = beg;
    for (; e + 4 <= end; e += 4) {
        uint2 u0 = *(const uint2*)(hhi + (size_t)g_col[e + 0] * D + lane * 4);
        uint2 u1 = *(const uint2*)(hhi + (size_t)g_col[e + 1] * D + lane * 4);
        uint2 u2 = *(const uint2*)(hhi + (size_t)g_col[e + 2] * D + lane * 4);
        uint2 u3 = *(const uint2*)(hhi + (size_t)g_col[e + 3] * D + lane * 4);
        float2 a0 = __bfloat1622float2(*(__nv_bfloat162*)&u0.x), b0 = __bfloat1622float2(*(__nv_bfloat162*)&u0.y);
        float2 a1 = __bfloat1622float2(*(__nv_bfloat162*)&u1.x), b1 = __bfloat1622float2(*(__nv_bfloat162*)&u1.y);
        float2 a2 = __bfloat1622float2(*(__nv_bfloat162*)&u2.x), b2 = __bfloat1622float2(*(__nv_bfloat162*)&u2.y);
        float2 a3 = __bfloat1622float2(*(__nv_bfloat162*)&u3.x), b3 = __bfloat1622float2(*(__nv_bfloat162*)&u3.y);
        acc.x += (a0.x + a1.x) + (a2.x + a3.x);
        acc.y += (a0.y + a1.y) + (a2.y + a3.y);
        acc.z += (b0.x + b1.x) + (b2.x + b3.x);
        acc.w += (b0.y + b1.y) + (b2.y + b3.y);
    }
    for (; e < end; e++) {
        uint2 u = *(const uint2*)(hhi + (size_t)g_col[e] * D + lane * 4);
        float2 a = __bfloat1622float2(*(__nv_bfloat162*)&u.x);
        float2 b = __bfloat1622float2(*(__nv_bfloat162*)&u.y);
        acc.x += a.x; acc.y += a.y; acc.z += b.x; acc.w += b.y;
    }
    float inv = g_invdeg[wid];
    acc.x *= inv; acc.y *= inv; acc.z *= inv; acc.w *= inv;
    *(float4*)(hn + (size_t)wid * D + lane * 4) = acc;
}

// ---------------- GEMM tile config (M tile = 64, 2 blocks/SM) ----------------
#define PITCH 272
#define MTILE 64
#define A_TILE_BYTES (MTILE * PITCH)   // 17408
#define B_TILE_BYTES (128 * PITCH)     // 34816
#define SMEM_TOTAL_BYTES (2 * A_TILE_BYTES + 2 * B_TILE_BYTES)  // 104448
#define STG_PITCH 132

__device__ __forceinline__ void load_split_A(const float* __restrict__ src, int row0, int n,
                                             char* As_hi, char* As_lo, int tid) {
    #pragma unroll 4
    for (int i = tid; i < 2048; i += 256) {
        int r = i >> 5, c = (i & 31) << 2;
        int gr = row0 + r;
        float4 v = make_float4(0.f, 0.f, 0.f, 0.f);
        if (gr < n) v = *(const float4*)(src + (size_t)gr * D + c);
        uint2 h, l;
        split_pack4(v, h, l);
        *(uint2*)(As_hi + r * PITCH + c * 2) = h;
        *(uint2*)(As_lo + r * PITCH + c * 2) = l;
    }
}

// A-load straight from bf16 hi/lo pair arrays (no conversion)
__device__ __forceinline__ void load_A_pair(const __nv_bfloat16* __restrict__ hi,
                                            const __nv_bfloat16* __restrict__ lo,
                                            int row0, int n,
                                            char* As_hi, char* As_lo, int tid) {
    #pragma unroll 4
    for (int i = tid; i < 2048; i += 256) {
        int arr = i >> 10;          // 0 = hi, 1 = lo
        int j = i & 1023;
        int r = j >> 4, c = (j & 15) << 3;   // 8 bf16 per uint4
        int gr = row0 + r;
        uint4 v = make_uint4(0u, 0u, 0u, 0u);
        const __nv_bfloat16* src = arr ? lo : hi;
        if (gr < n) v = *(const uint4*)(src + (size_t)gr * D + c);
        char* dstbase = arr ? As_lo : As_hi;
        *(uint4*)(dstbase + r * PITCH + c * 2) = v;
    }
}

__device__ __forceinline__ void stage_split_A(const float* __restrict__ stg,
                                              char* As_hi, char* As_lo, int tid) {
    #pragma unroll 4
    for (int i = tid; i < 2048; i += 256) {
        int r = i >> 5, c = (i & 31) << 2;
        float4 v = *(const float4*)(stg + r * STG_PITCH + c);
        uint2 h, l;
        split_pack4(v, h, l);
        *(uint2*)(As_hi + r * PITCH + c * 2) = h;
        *(uint2*)(As_lo + r * PITCH + c * 2) = l;
    }
}

__device__ __forceinline__ void load_B_prepped(int slot, char* Bs_hi, char* Bs_lo, int tid) {
    const __nv_bfloat16* whi = g_Whi + (size_t)slot * 16384;
    const __nv_bfloat16* wlo = g_Wlo + (size_t)slot * 16384;
    #pragma unroll 4
    for (int i = tid; i < 2048; i += 256) {
        int r = i >> 4, c = (i & 15) << 3;
        *(uint4*)(Bs_hi + r * PITCH + c * 2) = *(const uint4*)(whi + r * D + c);
        *(uint4*)(Bs_lo + r * PITCH + c * 2) = *(const uint4*)(wlo + r * D + c);
    }
}

__device__ __forceinline__ void mma_mainloop(float acc[2][4][4], uint32_t a_hi0, uint32_t b_hi0) {
    #pragma unroll
    for (int k = 0; k < 8; k++) {
        uint32_t ah[2][4], al[2][4], bh[4][2], bl[4][2];
        #pragma unroll
        for (int nt = 0; nt < 4; nt++) {
            ldsm_x2t(bh[nt], b_hi0 + (uint32_t)k * (16 * PITCH) + nt * 16);
            ldsm_x2t(bl[nt], b_hi0 + B_TILE_BYTES + (uint32_t)k * (16 * PITCH) + nt * 16);
        }
        #pragma unroll
        for (int mt = 0; mt < 2; mt++) {
            ldsm_x4(ah[mt], a_hi0 + (uint32_t)mt * (16 * PITCH) + k * 32);
            ldsm_x4(al[mt], a_hi0 + A_TILE_BYTES + (uint32_t)mt * (16 * PITCH) + k * 32);
        }
        #pragma unroll
        for (int mt = 0; mt < 2; mt++)
            #pragma unroll
            for (int nt = 0; nt < 4; nt++) {
                mma_bf16(acc[mt][nt], ah[mt], bh[nt]);
                mma_bf16(acc[mt][nt], ah[mt], bl[nt]);
                mma_bf16(acc[mt][nt], al[mt], bh[nt]);
            }
    }
}

__device__ __forceinline__ void zero_acc(float acc[2][4][4]) {
    #pragma unroll
    for (int mt = 0; mt < 2; mt++)
        #pragma unroll
        for (int nt = 0; nt < 4; nt++)
            #pragma unroll
            for (int q = 0; q < 4; q++) acc[mt][nt][q] = 0.f;
}

// epilogue to bf16 hi/lo pair arrays (OUTMODE 0) or fp32 (OUTMODE 1)
template <int ACT, int OUTMODE>
__device__ __forceinline__ void epilogue(float acc[2][4][4], const float* __restrict__ bias,
                                         __nv_bfloat16* __restrict__ out_hi,
                                         __nv_bfloat16* __restrict__ out_lo,
                                         float* __restrict__ out_f32,
                                         int row0, int n, int wm, int wn, int lane) {
    int mrow = lane >> 2;
    int mcol = (lane & 3) * 2;
    #pragma unroll
    for (int mt = 0; mt < 2; mt++)
        #pragma unroll
        for (int half = 0; half < 2; half++) {
            int gr = row0 + wm + mt * 16 + mrow + half * 8;
            if (gr < n) {
                size_t rb = (size_t)gr * D;
                #pragma unroll
                for (int nt = 0; nt < 4; nt++) {
                    int col = wn + nt * 8 + mcol;
                    float x0 = acc[mt][nt][half * 2 + 0];
                    float x1 = acc[mt][nt][half * 2 + 1];
                    if (bias) { x0 += bias[col]; x1 += bias[col + 1]; }
                    if (ACT == 1)      { x0 = tanhf(x0); x1 = tanhf(x1); }
                    else if (ACT == 2) { x0 = x0 / (1.f + expf(-x0)); x1 = x1 / (1.f + expf(-x1)); }
                    if (OUTMODE == 0) {
                        uint32_t lo, hi = split_pack2(x0, x1, lo);
                        *(uint32_t*)(out_hi + rb + col) = hi;
                        *(uint32_t*)(out_lo + rb + col) = lo;
                    } else {
                        *(float2*)(out_f32 + rb + col) = make_float2(x0, x1);
                    }
                }
            }
        }
}

// ---------------- fused fc_in: pair_out = tanh(h@W1+b1)@W2 + b2 ----------------
__global__ void __launch_bounds__(256, 2)
fc_fused_kernel(const float* __restrict__ A, const float* __restrict__ b1,
                const float* __restrict__ b2,
                __nv_bfloat16* __restrict__ out_hi, __nv_bfloat16* __restrict__ out_lo, int n) {
    extern __shared__ char smem[];
    char* As_hi = smem;
    char* As_lo = smem + A_TILE_BYTES;
    char* Bs_hi = smem + 2 * A_TILE_BYTES;
    float* staging = (float*)(smem + 2 * A_TILE_BYTES);

    int tid = threadIdx.x, lane = tid & 31, wid = tid >> 5;
    int row0 = blockIdx.x * MTILE;
    int wm = (wid & 1) * 32;
    int wn = (wid >> 1) * 32;
    int mrow = lane >> 2;
    int mcol = (lane & 3) * 2;

    uint32_t a_hi0 = smem_u32(As_hi) + (uint32_t)(wm + (lane & 15)) * PITCH + (lane >> 4) * 16;
    uint32_t b_hi0 = smem_u32(Bs_hi) + (uint32_t)(lane & 15) * PITCH + wn * 2;

    float acc[2][4][4];
    zero_acc(acc);

    load_split_A(A, row0, n, As_hi, As_lo, tid);
    load_B_prepped(0, Bs_hi, Bs_hi + B_TILE_BYTES, tid);
    __syncthreads();
    mma_mainloop(acc, a_hi0, b_hi0);
    __syncthreads();

    #pragma unroll
    for (int mt = 0; mt < 2; mt++)
        #pragma unroll
        for (int half = 0; half < 2; half++) {
            int r = wm + mt * 16 + mrow + half * 8;
            #pragma unroll
            for (int nt = 0; nt < 4; nt++) {
                int col = wn + nt * 8 + mcol;
                staging[r * STG_PITCH + col]     = tanhf(acc[mt][nt][half * 2 + 0] + b1[col]);
                staging[r * STG_PITCH + col + 1] = tanhf(acc[mt][nt][half * 2 + 1] + b1[col + 1]);
            }
        }
    __syncthreads();

    stage_split_A(staging, As_hi, As_lo, tid);
    __syncthreads();

    load_B_prepped(1, Bs_hi, Bs_hi + B_TILE_BYTES, tid);
    zero_acc(acc);
    __syncthreads();

    mma_mainloop(acc, a_hi0, b_hi0);
    epilogue<0, 0>(acc, b2, out_hi, out_lo, nullptr, row0, n, wm, wn, lane);
}

// ---------------- fused SAGE layer: out = act(in@Ws + bias + hn@Wn) ----------------
// in as bf16 hi/lo pair; hn fp32; out as pair (OUTMODE 0) or fp32 (OUTMODE 1).
template <int ACT, int OUTMODE>
__global__ void __launch_bounds__(256, 2)
layer_kernel(const __nv_bfloat16* __restrict__ in_hi, const __nv_bfloat16* __restrict__ in_lo,
             const float* __restrict__ hn, int slot_self, int slot_neigh,
             const float* __restrict__ bias,
             __nv_bfloat16* __restrict__ out_hi, __nv_bfloat16* __restrict__ out_lo,
             float* __restrict__ out_f32, int n) {
    extern __shared__ char smem[];
    char* As_hi = smem;
    char* As_lo = smem + A_TILE_BYTES;
    char* Bs_hi = smem + 2 * A_TILE_BYTES;

    int tid = threadIdx.x, lane = tid & 31, wid = tid >> 5;
    int row0 = blockIdx.x * MTILE;
    int wm = (wid & 1) * 32;
    int wn = (wid >> 1) * 32;

    uint32_t a_hi0 = smem_u32(As_hi) + (uint32_t)(wm + (lane & 15)) * PITCH + (lane >> 4) * 16;
    uint32_t b_hi0 = smem_u32(Bs_hi) + (uint32_t)(lane & 15) * PITCH + wn * 2;

    float acc[2][4][4];
    zero_acc(acc);

    // phase 1: self term (A from bf16 pair — zero conversion)
    load_A_pair(in_hi, in_lo, row0, n, As_hi, As_lo, tid);
    load_B_prepped(slot_self, Bs_hi, Bs_hi + B_TILE_BYTES, tid);
    __syncthreads();
    mma_mainloop(acc, a_hi0, b_hi0);
    __syncthreads();

    // phase 2: neighbor term (A from hn fp32 via split)
    load_split_A(hn, row0, n, As_hi, As_lo, tid);
    load_B_prepped(slot_neigh, Bs_hi, Bs_hi + B_TILE_BYTES, tid);
    __syncthreads();
    mma_mainloop(acc, a_hi0, b_hi0);

    epilogue<ACT, OUTMODE>(acc, bias, out_hi, out_lo, out_f32, row0, n, wm, wn, lane);
}

// ---------------- launch ----------------
extern "C" void kernel_launch(void* const* d_in, const int* in_sizes, int n_in,
                              void* d_out, int out_size) {
    const float* h_in    = (const float*)d_in[0];
    const int*   src     = (const int*)  d_in[1];
    const int*   dst     = (const int*)  d_in[2];
    const float* W_in1   = (const float*)d_in[3];
    const float* b_in1   = (const float*)d_in[4];
    const float* W_in2   = (const float*)d_in[5];
    const float* b_in2   = (const float*)d_in[6];
    const float* W_self  = (const float*)d_in[7];
    const float* b_self  = (const float*)d_in[8];
    const float* W_neigh = (const float*)d_in[9];
    float* out = (float*)d_out;

    cudaFuncSetAttribute(fc_fused_kernel,    cudaFuncAttributeMaxDynamicSharedMemorySize, SMEM_TOTAL_BYTES);
    cudaFuncSetAttribute(layer_kernel<2, 0>, cudaFuncAttributeMaxDynamicSharedMemorySize, SMEM_TOTAL_BYTES);
    cudaFuncSetAttribute(layer_kernel<1, 1>, cudaFuncAttributeMaxDynamicSharedMemorySize, SMEM_TOTAL_BYTES);

    __nv_bfloat16 *hiA = nullptr, *loA = nullptr, *hiB = nullptr, *loB = nullptr;
    float* hn = nullptr;
    cudaGetSymbolAddress((void**)&hiA, g_hiA);
    cudaGetSymbolAddress((void**)&loA, g_loA);
    cudaGetSymbolAddress((void**)&hiB, g_hiB);
    cudaGetSymbolAddress((void**)&loB, g_loB);
    cudaGetSymbolAddress((void**)&hn,  g_hn);

    const int GEMM_GRID = (N_NODES + MTILE - 1) / MTILE;  // 782
    const int EB = (N_EDGES + 255) / 256;
    const int AGG_GRID = (N_NODES * 32 + 255) / 256;

    // ---- prep (W split + zero deg) then CSR build ----
    prep_kernel<<<512, 256>>>(W_in1, W_in2, W_self, W_neigh);
    count_kernel<<<EB, 256>>>(dst);
    scan_kernel<<<1, 1024>>>();
    fill_kernel<<<EB, 256>>>(src, dst);

    // ---- fc_in fused: pairA = tanh(h@W1+b1)@W2 + b2 ----
    fc_fused_kernel<<<GEMM_GRID, 256, SMEM_TOTAL_BYTES>>>(h_in, b_in1, b_in2, hiA, loA, N_NODES);

    // ---- 3 SAGE layers: bf16-hi gather + fused dual-GEMM ----
    agg_bf16_kernel<<<AGG_GRID, 256>>>(hiA, hn);
    layer_kernel<2, 0><<<GEMM_GRID, 256, SMEM_TOTAL_BYTES>>>(hiA, loA, hn, 2, 5, b_self + 0 * D,
                                                             hiB, loB, nullptr, N_NODES);

    agg_bf16_kernel<<<AGG_GRID, 256>>>(hiB, hn);
    layer_kernel<2, 0><<<GEMM_GRID, 256, SMEM_TOTAL_BYTES>>>(hiB, loB, hn, 3, 6, b_self + 1 * D,
                                                             hiA, loA, nullptr, N_NODES);

    agg_bf16_kernel<<<AGG_GRID, 256>>>(hiA, hn);
    layer_kernel<1, 1><<<GEMM_GRID, 256, SMEM_TOTAL_BYTES>>>(hiA, loA, hn, 4, 7, b_self + 2 * D,
                                                             nullptr, nullptr, out, N_NODES);
}